// round 1
// baseline (speedup 1.0000x reference)
#include <cuda_runtime.h>
#include <math.h>

// Problem constants
#define SS 64
#define BB 32
#define DM 586
#define DE 583
#define NL 4
#define K1 17
#define CO1 16
#define P1LEN 114
#define KP 21       // combined conv1+pool kernel length
#define CO2 8
#define P2LEN 38
#define CO3 32
#define T3 36
#define NV 128
#define XSTR 304
#define PHLEN 57

// Scratch (no allocations allowed)
__device__ float g_x0[SS*BB*DM];
__device__ float g_mean[SS];
__device__ float g_var[SS];
__device__ float g_A[SS];
__device__ float g_C[SS];
__device__ float g_w1p[CO1*BB*KP];    // [co][ci][m]
__device__ float g_w1ps[BB*KP*16];    // [ci*21+m][co]  (co-fastest for conflict-free LDS)
__device__ float g_wsum1[CO1];
__device__ float g_out1p[SS*CO1*P1LEN];

// ---------------------------------------------------------------------------
// Kernel A: embedding gather (*sqrt(D)) + pos concat -> g_x0 ; per-s mean/var
// ---------------------------------------------------------------------------
__global__ void kA(const int* __restrict__ tokens, const float* __restrict__ emb,
                   const float* __restrict__ pos) {
    int s = blockIdx.x;
    int tid = threadIdx.x;
    const float scale = sqrtf(586.0f);
    float sum = 0.f, sq = 0.f;
    for (int idx = tid; idx < BB*DM; idx += blockDim.x) {
        int b = idx / DM;
        int d = idx - b*DM;
        float v;
        if (d < DE) {
            int tok = tokens[s*BB + b];
            v = emb[(size_t)tok*DE + d] * scale;
        } else {
            v = pos[(s*BB + b)*3 + (d - DE)];
        }
        g_x0[s*BB*DM + idx] = v;
        sum += v; sq += v*v;
    }
    __shared__ float sh[512];
    sh[tid] = sum; sh[256 + tid] = sq;
    __syncthreads();
    for (int o = 128; o > 0; o >>= 1) {
        if (tid < o) { sh[tid] += sh[tid+o]; sh[256+tid] += sh[256+tid+o]; }
        __syncthreads();
    }
    if (tid == 0) {
        float invN = 1.f / (float)(BB*DM);
        float m = sh[0] * invN;
        g_mean[s] = m;
        g_var[s]  = sh[256] * invN - m*m;   // biased var, matches reference
    }
}

// ---------------------------------------------------------------------------
// Kernel B: fold 4 BN layers into per-s affine (A,C); build combined conv1+pool
// weights w1p (kernel 21, stride 5) and their per-co sums.
// ---------------------------------------------------------------------------
__global__ void kB(const float* __restrict__ gamma, const float* __restrict__ beta,
                   const float* __restrict__ w1) {
    int tid = threadIdx.x;
    if (tid < SS) {
        float m = g_mean[tid], v = g_var[tid];
        float A = 1.f, C = 0.f;
        #pragma unroll
        for (int l = 0; l < NL; l++) {
            float g  = gamma[l*SS + tid];
            float bb = beta[l*SS + tid];
            float inv = rsqrtf(v + 1e-5f);
            float a = g * inv;
            float c = bb - a * m;
            A = a * A;
            C = a * C + c;
            m = bb;          // mean after this BN layer
            v = a * a * v;   // var  after this BN layer
        }
        g_A[tid] = A; g_C[tid] = C;
    }
    // Combined weights: w1p[co][ci][m] = (1/5) * sum_{j=max(0,m-16)}^{min(4,m)} w1[co][ci][m-j]
    for (int idx = tid; idx < CO1*BB*KP; idx += blockDim.x) {
        int co = idx / (BB*KP);
        int r  = idx - co*(BB*KP);
        int ci = r / KP;
        int m  = r - ci*KP;
        int jlo = m - (K1-1); if (jlo < 0) jlo = 0;
        int jhi = m;          if (jhi > 4) jhi = 4;
        float acc = 0.f;
        for (int j = jlo; j <= jhi; j++)
            acc += w1[(co*BB + ci)*K1 + (m - j)];
        float val = acc * 0.2f;
        g_w1p[idx] = val;
        g_w1ps[(ci*KP + m)*16 + co] = val;
    }
    __syncthreads();
    if (tid < CO1) {
        float sum = 0.f;
        for (int i = 0; i < BB*KP; i++) sum += g_w1p[tid*BB*KP + i];
        g_wsum1[tid] = sum;
    }
}

// ---------------------------------------------------------------------------
// Kernel C: fused conv1+avgpool1 as a stride-5, K=21 conv.
// grid = 128 (s x p-half), block = 128. Register tile: 2 co x 4 p.
// Affine (A,C) folded into epilogue: out = A*raw + (C*wsum + b1).
// ---------------------------------------------------------------------------
__global__ void kC(const float* __restrict__ b1) {
    int bx = blockIdx.x;
    int s  = bx >> 1;
    int ph = bx & 1;
    int p0 = ph * PHLEN;
    int d0 = p0 * 5;

    extern __shared__ float sm[];
    float* xs = sm;                        // BB*XSTR + 64 pad
    float* ws = sm + BB*XSTR + 64;         // 672*16

    int tid = threadIdx.x;
    // Load x slice (301 valid cols per ci, padded to XSTR)
    for (int idx = tid; idx < BB*XSTR; idx += 128) {
        int ci = idx / XSTR;
        int dd = idx - ci*XSTR;
        float v = 0.f;
        if (dd < 301) v = g_x0[(s*BB + ci)*DM + d0 + dd];
        xs[idx] = v;
    }
    if (tid < 64) xs[BB*XSTR + tid] = 0.f;  // pad for harmless over-read on ragged tile
    for (int idx = tid; idx < BB*KP*16; idx += 128) ws[idx] = g_w1ps[idx];
    __syncthreads();

    int pt  = tid >> 3;   // 0..15 (15 invalid) -> warp spans Δpt<=3: conflict-free x LDS
    int cop = tid & 7;    // 0..7 co-pairs
    if (pt < 15) {
        int pl0 = pt * 4;
        int co0 = cop * 2;
        float acc0[4] = {0.f,0.f,0.f,0.f};
        float acc1[4] = {0.f,0.f,0.f,0.f};
        const float* xbase = xs + 5*pl0;
        #pragma unroll 2
        for (int ci = 0; ci < BB; ci++) {
            const float* xr = xbase + ci*XSTR;
            float xw[36];
            #pragma unroll
            for (int i = 0; i < 36; i++) xw[i] = xr[i];
            const float* wp = ws + ci*KP*16 + co0;
            #pragma unroll
            for (int m = 0; m < KP; m++) {
                float2 w = *(const float2*)(wp + m*16);
                #pragma unroll
                for (int q = 0; q < 4; q++) {
                    float xv = xw[5*q + m];
                    acc0[q] += w.x * xv;
                    acc1[q] += w.y * xv;
                }
            }
        }
        float A  = g_A[s];
        float Cc = g_C[s];
        float bias0 = Cc * g_wsum1[co0]   + b1[co0];
        float bias1 = Cc * g_wsum1[co0+1] + b1[co0+1];
        #pragma unroll
        for (int q = 0; q < 4; q++) {
            int pl = pl0 + q;
            if (pl < PHLEN) {
                int p = p0 + pl;
                g_out1p[(s*CO1 + co0  )*P1LEN + p] = A*acc0[q] + bias0;
                g_out1p[(s*CO1 + co0+1)*P1LEN + p] = A*acc1[q] + bias1;
            }
        }
    }
}

// ---------------------------------------------------------------------------
// Kernel D: avgpool2 -> conv2(1x1) -> conv3(K=3) -> proj(128x36) -> argmax.
// One block per s (64 blocks, 128 threads). Pool/conv2 swap is exact (1x1 linear).
// ---------------------------------------------------------------------------
__global__ void kD(const float* __restrict__ w2, const float* __restrict__ b2,
                   const float* __restrict__ w3, const float* __restrict__ b3,
                   const float* __restrict__ wl, const float* __restrict__ bl,
                   float* __restrict__ out) {
    int s = blockIdx.x;
    int tid = threadIdx.x;
    __shared__ float o1[CO1*P1LEN];
    __shared__ float wls[NV*T3];
    __shared__ float bls[NV];
    __shared__ float o2[CO2*P2LEN];
    __shared__ float o3[CO3*T3];

    for (int i = tid; i < CO1*P1LEN; i += 128) o1[i] = g_out1p[s*CO1*P1LEN + i];
    for (int i = tid; i < NV*T3;    i += 128) wls[i] = wl[i];
    if (tid < NV) bls[tid] = bl[tid];
    __syncthreads();

    // avgpool(3) then conv2 1x1 (commutes with reference conv2->pool)
    for (int i = tid; i < CO2*P2LEN; i += 128) {
        int c8 = i / P2LEN;
        int q  = i - c8*P2LEN;
        float acc = 0.f;
        #pragma unroll
        for (int ci = 0; ci < CO1; ci++) {
            const float* r = o1 + ci*P1LEN + 3*q;
            acc += w2[c8*CO1 + ci] * (r[0] + r[1] + r[2]);
        }
        o2[i] = acc * (1.f/3.f) + b2[c8];
    }
    __syncthreads();

    // conv3: (8,38) -> (32,36), K=3
    for (int i = tid; i < CO3*T3; i += 128) {
        int co = i / T3;
        int t  = i - co*T3;
        float acc = b3[co];
        #pragma unroll
        for (int c8 = 0; c8 < CO2; c8++) {
            const float* r = o2 + c8*P2LEN + t;
            const float* w = w3 + (co*CO2 + c8)*3;
            acc += w[0]*r[0] + w[1]*r[1] + w[2]*r[2];
        }
        o3[i] = acc;
    }
    __syncthreads();

    // projection to 128 vocab + argmax (first-max semantics like jnp.argmax)
    int c   = tid >> 2;   // output channel 0..31
    int seg = tid & 3;    // vocab segment of 32
    float bestv = -3.4e38f;
    int   besti = 0;
    const float* orow = o3 + c*T3;
    for (int v = seg*32; v < seg*32 + 32; v++) {
        float d = bls[v];
        const float* wr = wls + v*T3;
        #pragma unroll
        for (int k = 0; k < T3; k++) d += orow[k] * wr[k];
        if (d > bestv) { bestv = d; besti = v; }  // strict > keeps first max
    }
    // reduce over the 4 segment lanes (groups of 4 aligned within warp)
    #pragma unroll
    for (int off = 2; off >= 1; off >>= 1) {
        float ov = __shfl_down_sync(0xffffffffu, bestv, off);
        int   oi = __shfl_down_sync(0xffffffffu, besti, off);
        if (ov > bestv || (ov == bestv && oi < besti)) { bestv = ov; besti = oi; }
    }
    if (seg == 0) out[s*BB + c] = (float)besti;
}

// ---------------------------------------------------------------------------
extern "C" void kernel_launch(void* const* d_in, const int* in_sizes, int n_in,
                              void* d_out, int out_size) {
    const int*   tokens = (const int*)  d_in[0];
    const float* emb    = (const float*)d_in[1];
    const float* pos    = (const float*)d_in[2];
    const float* gamma  = (const float*)d_in[3];
    const float* beta   = (const float*)d_in[4];
    const float* w1     = (const float*)d_in[5];
    const float* b1     = (const float*)d_in[6];
    const float* w2     = (const float*)d_in[7];
    const float* b2     = (const float*)d_in[8];
    const float* w3     = (const float*)d_in[9];
    const float* b3     = (const float*)d_in[10];
    const float* wl     = (const float*)d_in[11];
    const float* bl     = (const float*)d_in[12];
    float* out = (float*)d_out;

    size_t shC = (size_t)(BB*XSTR + 64 + BB*KP*16) * sizeof(float);  // ~82 KB
    cudaFuncSetAttribute(kC, cudaFuncAttributeMaxDynamicSharedMemorySize, (int)shC);

    kA<<<SS, 256>>>(tokens, emb, pos);
    kB<<<1, 256>>>(gamma, beta, w1);
    kC<<<128, 128, shC>>>(b1);
    kD<<<SS, 128>>>(w2, b2, w3, b3, wl, bl, out);
}

// round 2
// speedup vs baseline: 2.0798x; 2.0798x over previous
#include <cuda_runtime.h>
#include <math.h>

// Problem constants
#define SS 64
#define BB 32
#define DM 586
#define DE 583
#define NL 4
#define K1 17
#define CO1 16
#define P1LEN 114
#define KP 21       // combined conv1+pool kernel length
#define CO2 8
#define P2LEN 38
#define CO3 32
#define T3 36
#define NV 128
#define XSTR 180    // smem x row stride in kC

// Scratch (no allocations allowed)
__device__ float g_x0[SS*BB*DM];
__device__ float g_A[SS];
__device__ float g_C[SS];
__device__ float g_w1ps[BB*KP*16];    // [ci*21+m][co]  (co-fastest, conflict-free LDS)
__device__ float g_wsum1[CO1];
__device__ float g_out1p[SS*CO1*P1LEN];

// ---------------------------------------------------------------------------
// Kernel A (blocks 0..63): embedding gather (*sqrt(D)) + pos concat -> g_x0;
// per-s mean/var; fold 4 BN layers into per-s affine (A,C) in-block.
// Kernel A (blocks 64..79): build combined conv1+pool weights (co = bx-64)
// and wsum1[co] = sum of original w1[co] (exact via pooling coverage identity).
// ---------------------------------------------------------------------------
__global__ void kA(const int* __restrict__ tokens, const float* __restrict__ emb,
                   const float* __restrict__ pos,
                   const float* __restrict__ gamma, const float* __restrict__ beta,
                   const float* __restrict__ w1) {
    int tid = threadIdx.x;
    __shared__ float sh[512];

    if (blockIdx.x < SS) {
        int s = blockIdx.x;
        const float scale = sqrtf(586.0f);
        float sum = 0.f, sq = 0.f;
        #pragma unroll 4
        for (int idx = tid; idx < BB*DM; idx += 256) {
            int b = idx / DM;
            int d = idx - b*DM;
            float v;
            if (d < DE) {
                int tok = tokens[s*BB + b];
                v = emb[(size_t)tok*DE + d] * scale;
            } else {
                v = pos[(s*BB + b)*3 + (d - DE)];
            }
            g_x0[s*BB*DM + idx] = v;
            sum += v; sq += v*v;
        }
        sh[tid] = sum; sh[256 + tid] = sq;
        __syncthreads();
        for (int o = 128; o > 0; o >>= 1) {
            if (tid < o) { sh[tid] += sh[tid+o]; sh[256+tid] += sh[256+tid+o]; }
            __syncthreads();
        }
        if (tid == 0) {
            float invN = 1.f / (float)(BB*DM);
            float m = sh[0] * invN;
            float v = sh[256] * invN - m*m;   // biased var, matches reference
            float A = 1.f, C = 0.f;
            #pragma unroll
            for (int l = 0; l < NL; l++) {
                float g  = gamma[l*SS + s];
                float bb = beta[l*SS + s];
                float inv = rsqrtf(v + 1e-5f);
                float a = g * inv;
                float c = bb - a * m;
                A = a * A;
                C = a * C + c;
                m = bb;          // mean after this BN layer
                v = a * a * v;   // var  after this BN layer
            }
            g_A[s] = A; g_C[s] = C;
        }
    } else {
        // weight prep for one output channel
        int co = blockIdx.x - SS;
        const float* wrow = w1 + co*BB*K1;   // 544 floats
        // combined weights: w1p[ci][m] = 0.2 * sum_{j} w1[ci][m-j], j in [max(0,m-16), min(4,m)]
        for (int e = tid; e < BB*KP; e += 256) {
            int ci = e / KP;
            int m  = e - ci*KP;
            int jlo = m - (K1-1); if (jlo < 0) jlo = 0;
            int jhi = m;          if (jhi > 4) jhi = 4;
            float acc = 0.f;
            for (int j = jlo; j <= jhi; j++)
                acc += wrow[ci*K1 + (m - j)];
            g_w1ps[e*16 + co] = acc * 0.2f;
        }
        // wsum1[co] = sum of all 544 raw weights (coverage identity: each tap hit 5x * 1/5)
        float p = 0.f;
        for (int i = tid; i < BB*K1; i += 256) p += wrow[i];
        sh[tid] = p;
        __syncthreads();
        for (int o = 128; o > 0; o >>= 1) {
            if (tid < o) sh[tid] += sh[tid+o];
            __syncthreads();
        }
        if (tid == 0) g_wsum1[co] = sh[0];
    }
}

// ---------------------------------------------------------------------------
// Kernel C: fused conv1+avgpool1 as a stride-5, K=21 conv.
// grid = 256 (64 s x 4 p-chunks of {29,29,28,28}), block = 128.
// Register tile: 2 co x 2 p. Affine (A,C) folded into epilogue.
// ---------------------------------------------------------------------------
__global__ void kC(const float* __restrict__ b1) {
    int bx = blockIdx.x;
    int s  = bx >> 2;
    int cc = bx & 3;
    int p0 = (cc < 2) ? cc*29 : 58 + (cc-2)*28;
    int CH = (cc < 2) ? 29 : 28;
    int d0 = p0 * 5;
    int span = (CH-1)*5 + KP;  // 161 or 156 valid input cols

    extern __shared__ float sm[];
    float* xs = sm;                    // BB * XSTR
    float* ws = sm + BB*XSTR;          // 672 * 16

    int tid = threadIdx.x;
    // Load x slice (span valid cols per ci, zero-padded to XSTR)
    for (int idx = tid; idx < BB*XSTR; idx += 128) {
        int ci = idx / XSTR;
        int dd = idx - ci*XSTR;
        float v = 0.f;
        if (dd < span) v = g_x0[(s*BB + ci)*DM + d0 + dd];
        xs[idx] = v;
    }
    // Load weights (vectorized)
    {
        const float4* wsrc = (const float4*)g_w1ps;
        float4* wdst = (float4*)ws;
        for (int idx = tid; idx < BB*KP*4; idx += 128) wdst[idx] = wsrc[idx];
    }
    __syncthreads();

    int pt  = tid >> 3;   // 0..15 ; warp spans 4 pt -> x LDS stride 10 words, conflict-free
    int cop = tid & 7;    // 0..7 co-pairs
    int pl0 = pt * 2;
    int co0 = cop * 2;
    float acc00 = 0.f, acc01 = 0.f, acc10 = 0.f, acc11 = 0.f;
    const float* xbase = xs + 5*pl0;
    #pragma unroll 2
    for (int ci = 0; ci < BB; ci++) {
        const float* xr = xbase + ci*XSTR;
        float xw[26];
        #pragma unroll
        for (int i = 0; i < 26; i++) xw[i] = xr[i];
        const float* wp = ws + ci*KP*16 + co0;
        #pragma unroll
        for (int m = 0; m < KP; m++) {
            float2 w = *(const float2*)(wp + m*16);
            float x0v = xw[m];
            float x1v = xw[m+5];
            acc00 += w.x * x0v;
            acc01 += w.y * x0v;
            acc10 += w.x * x1v;
            acc11 += w.y * x1v;
        }
    }
    float A  = g_A[s];
    float Cc = g_C[s];
    float bias0 = Cc * g_wsum1[co0]   + b1[co0];
    float bias1 = Cc * g_wsum1[co0+1] + b1[co0+1];
    if (pl0 < CH) {
        int p = p0 + pl0;
        g_out1p[(s*CO1 + co0  )*P1LEN + p] = A*acc00 + bias0;
        g_out1p[(s*CO1 + co0+1)*P1LEN + p] = A*acc01 + bias1;
    }
    if (pl0 + 1 < CH) {
        int p = p0 + pl0 + 1;
        g_out1p[(s*CO1 + co0  )*P1LEN + p] = A*acc10 + bias0;
        g_out1p[(s*CO1 + co0+1)*P1LEN + p] = A*acc11 + bias1;
    }
}

// ---------------------------------------------------------------------------
// Kernel D: avgpool2 -> conv2(1x1) -> conv3(K=3) -> proj(128x36) -> argmax.
// grid = 64 (one per s), block = 256.
// ---------------------------------------------------------------------------
__global__ void kD(const float* __restrict__ w2, const float* __restrict__ b2,
                   const float* __restrict__ w3, const float* __restrict__ b3,
                   const float* __restrict__ wl, const float* __restrict__ bl,
                   float* __restrict__ out) {
    int s = blockIdx.x;
    int tid = threadIdx.x;
    __shared__ float o1[CO1*P1LEN];
    __shared__ float wls[NV*T3];
    __shared__ float bls[NV];
    __shared__ float o2[CO2*P2LEN];
    __shared__ float o3[CO3*T3];

    for (int i = tid; i < CO1*P1LEN; i += 256) o1[i] = g_out1p[s*CO1*P1LEN + i];
    for (int i = tid; i < NV*T3;    i += 256) wls[i] = wl[i];
    if (tid < NV) bls[tid] = bl[tid];
    __syncthreads();

    // avgpool(3) then conv2 1x1 (commutes with reference conv2->pool)
    for (int i = tid; i < CO2*P2LEN; i += 256) {
        int c8 = i / P2LEN;
        int q  = i - c8*P2LEN;
        float acc = 0.f;
        #pragma unroll
        for (int ci = 0; ci < CO1; ci++) {
            const float* r = o1 + ci*P1LEN + 3*q;
            acc += w2[c8*CO1 + ci] * (r[0] + r[1] + r[2]);
        }
        o2[i] = acc * (1.f/3.f) + b2[c8];
    }
    __syncthreads();

    // conv3: (8,38) -> (32,36), K=3
    for (int i = tid; i < CO3*T3; i += 256) {
        int co = i / T3;
        int t  = i - co*T3;
        float acc = b3[co];
        #pragma unroll
        for (int c8 = 0; c8 < CO2; c8++) {
            const float* r = o2 + c8*P2LEN + t;
            const float* w = w3 + (co*CO2 + c8)*3;
            acc += w[0]*r[0] + w[1]*r[1] + w[2]*r[2];
        }
        o3[i] = acc;
    }
    __syncthreads();

    // projection to 128 vocab + argmax (first-max semantics like jnp.argmax)
    // layout: c = tid>>3 (channel), vl = tid&7 (vocab lane); v = vl + 8*i.
    // wls LDS: 8 distinct rows per warp, bank = (36*vl+k)%32 = (4*vl+k)%32 distinct -> conflict-free.
    int c  = tid >> 3;
    int vl = tid & 7;
    float orow[T3];
    #pragma unroll
    for (int k = 0; k < T3; k++) orow[k] = o3[c*T3 + k];

    float bestv = -3.4e38f;
    int   besti = 0;
    #pragma unroll 2
    for (int i = 0; i < 16; i++) {
        int v = vl + 8*i;
        float d = bls[v];
        const float* wr = wls + v*T3;
        #pragma unroll
        for (int k = 0; k < T3; k++) d += orow[k] * wr[k];
        if (d > bestv) { bestv = d; besti = v; }  // strict > keeps first max within lane
    }
    // reduce over the 8 vocab lanes (aligned groups of 8 within warp)
    #pragma unroll
    for (int off = 4; off >= 1; off >>= 1) {
        float ov = __shfl_down_sync(0xffffffffu, bestv, off);
        int   oi = __shfl_down_sync(0xffffffffu, besti, off);
        if (ov > bestv || (ov == bestv && oi < besti)) { bestv = ov; besti = oi; }
    }
    if (vl == 0) out[s*BB + c] = (float)besti;
}

// ---------------------------------------------------------------------------
extern "C" void kernel_launch(void* const* d_in, const int* in_sizes, int n_in,
                              void* d_out, int out_size) {
    const int*   tokens = (const int*)  d_in[0];
    const float* emb    = (const float*)d_in[1];
    const float* pos    = (const float*)d_in[2];
    const float* gamma  = (const float*)d_in[3];
    const float* beta   = (const float*)d_in[4];
    const float* w1     = (const float*)d_in[5];
    const float* b1     = (const float*)d_in[6];
    const float* w2     = (const float*)d_in[7];
    const float* b2     = (const float*)d_in[8];
    const float* w3     = (const float*)d_in[9];
    const float* b3     = (const float*)d_in[10];
    const float* wl     = (const float*)d_in[11];
    const float* bl     = (const float*)d_in[12];
    float* out = (float*)d_out;

    size_t shC = (size_t)(BB*XSTR + BB*KP*16) * sizeof(float);  // ~65 KB
    cudaFuncSetAttribute(kC, cudaFuncAttributeMaxDynamicSharedMemorySize, (int)shC);

    kA<<<SS + CO1, 256>>>(tokens, emb, pos, gamma, beta, w1);
    kC<<<256, 128, shC>>>(b1);
    kD<<<SS, 256>>>(w2, b2, w3, b3, wl, bl, out);
}